// round 5
// baseline (speedup 1.0000x reference)
#include <cuda_runtime.h>
#include <math.h>
#include <stdint.h>

#define BATCH  256
#define D      512
#define S      196

// device scratch (no allocs allowed)
__device__ float g_vp[4][BATCH][D];       // k-quarter partials of v = u @ W  (2 MB)
__device__ float g_rai[4 * BATCH * 256];  // per-quarter partial logits, stride 256

// packed fp32x2 helpers (Blackwell): full fp32 precision, 2 MAC per instr
__device__ __forceinline__ uint64_t fma2(uint64_t a, uint64_t b, uint64_t c) {
    uint64_t d;
    asm("fma.rn.f32x2 %0, %1, %2, %3;" : "=l"(d) : "l"(a), "l"(b), "l"(c));
    return d;
}
__device__ __forceinline__ uint64_t pack2(float lo, float hi) {
    uint64_t r;
    asm("mov.b64 %0, {%1, %2};" : "=l"(r) : "f"(lo), "f"(hi));
    return r;
}
__device__ __forceinline__ void unpack2(uint64_t v, float& lo, float& hi) {
    asm("mov.b64 {%0, %1}, %2;" : "=f"(lo), "=f"(hi) : "l"(v));
}

// ---------------------------------------------------------------------------
// GEMM partials: g_vp[kq][b][d] = sum_{e in kq-quarter} u[b,e] * W[e,d],
//   u[b,e] = ctrl[b,e] * w_attn[e].
// Grid (4 d-tiles, 16 b-tiles, 4 k-quarters) = 256 CTAs, 256 threads.
// Thread: dl = tid&127 (one d col), eh = tid>>7 (2-way split of the 128-e
// quarter). 16 batches per CTA -> 16 MAC per (LDG + pack + 4 LDS.128).
// ---------------------------------------------------------------------------
__global__ __launch_bounds__(256) void gemm_kernel(
    const float* __restrict__ ctrl,
    const float* __restrict__ W,       // [e, d] row-major
    const float* __restrict__ w_attn)
{
    __shared__ __align__(16) float sm[4096];   // phase1: u_s[el*16+j] (8KB); phase2: partials (16KB)

    const int tid = threadIdx.x;
    const int dl  = tid & 127;
    const int eh  = tid >> 7;          // 0/1
    const int dq  = blockIdx.x;        // 0..3
    const int b0  = blockIdx.y * 16;
    const int kq  = blockIdx.z;        // 0..3
    const int d   = dq * 128 + dl;
    const int e0  = kq * 128;

    // u_s[el*16 + j] = ctrl[b0+j, e0+el] * w_attn[e0+el]
    for (int idx = tid; idx < 2048; idx += 256) {
        int el = idx >> 4, j = idx & 15;
        sm[idx] = ctrl[(b0 + j) * D + e0 + el] * w_attn[e0 + el];
    }
    __syncthreads();

    uint64_t acc[8];
#pragma unroll
    for (int p = 0; p < 8; p++) acc[p] = 0ull;

    const int elbase = eh * 64;
#pragma unroll 8
    for (int i = 0; i < 64; i++) {
        const int el = elbase + i;
        float wv = W[(e0 + el) * D + d];           // coalesced 128B/warp, L2
        uint64_t ww = pack2(wv, wv);
        const ulonglong2* up = reinterpret_cast<const ulonglong2*>(&sm[el * 16]);
        ulonglong2 u01 = up[0];                    // broadcast LDS.128
        ulonglong2 u23 = up[1];
        ulonglong2 u45 = up[2];
        ulonglong2 u67 = up[3];
        acc[0] = fma2(ww, u01.x, acc[0]);  acc[1] = fma2(ww, u01.y, acc[1]);
        acc[2] = fma2(ww, u23.x, acc[2]);  acc[3] = fma2(ww, u23.y, acc[3]);
        acc[4] = fma2(ww, u45.x, acc[4]);  acc[5] = fma2(ww, u45.y, acc[5]);
        acc[6] = fma2(ww, u67.x, acc[6]);  acc[7] = fma2(ww, u67.y, acc[7]);
    }
    __syncthreads();

    // spill partials: sm[eh*2048 + j*128 + dl], j = 0..15
#pragma unroll
    for (int p = 0; p < 8; p++) {
        float lo, hi;
        unpack2(acc[p], lo, hi);
        sm[eh * 2048 + (2 * p) * 128 + dl]     = lo;
        sm[eh * 2048 + (2 * p + 1) * 128 + dl] = hi;
    }
    __syncthreads();

    for (int o = tid; o < 2048; o += 256) {
        float v = sm[o] + sm[2048 + o];
        int j  = o >> 7;
        int dd = o & 127;
        g_vp[kq][b0 + j][dq * 128 + dd] = v;
    }
}

// ---------------------------------------------------------------------------
// Kernel A: partial logits (finalize of w fused into the w_s load).
// Grid 1024 = (b, quarter): each CTA owns 128 d-rows, 8 warps, warp-per-row
// float4 loads. Streams kb from DRAM exactly once.
// ---------------------------------------------------------------------------
__global__ __launch_bounds__(256) void logits_kernel(
    const float* __restrict__ kb,      // [B, D, S]
    const float* __restrict__ memory,
    const float* __restrict__ ctrl,
    const float* __restrict__ w_attn)
{
    const int q    = blockIdx.x & 3;
    const int b    = blockIdx.x >> 2;
    const int tid  = threadIdx.x;
    const int wid  = tid >> 5;
    const int lane = tid & 31;
    const int l2   = lane < 17 ? lane : 16;     // clamp second segment
    const float mB = lane < 17 ? 1.f : 0.f;

    __shared__ float w_s[128];
    __shared__ __align__(16) float part[8][200];

    const float* __restrict__ base = kb + (size_t)b * (D * S) + (size_t)q * (128 * S);

    // fused finalize: w = memory * (sum of 4 k-quarter partials) + ctrl * w_attn
    if (tid < 128) {
        const int dg = q * 128 + tid;
        float v = g_vp[0][b][dg] + g_vp[1][b][dg] + g_vp[2][b][dg] + g_vp[3][b][dg];
        w_s[tid] = memory[b * D + dg] * v + ctrl[b * D + dg] * w_attn[dg];
    }
    __syncthreads();

    float4 accA = make_float4(0.f, 0.f, 0.f, 0.f);
    float4 accB = make_float4(0.f, 0.f, 0.f, 0.f);

#pragma unroll 4
    for (int r = wid; r < 128; r += 8) {
        const float wv = w_s[r];
        const float4* __restrict__ row = reinterpret_cast<const float4*>(base + r * S);
        float4 va = row[lane];          // s = 4*lane..+3       (s < 128)
        float4 vb = row[32 + l2];       // s = 128+4*l2..+3     (s < 196)
        accA.x += wv * va.x;  accA.y += wv * va.y;
        accA.z += wv * va.z;  accA.w += wv * va.w;
        float wb = wv * mB;
        accB.x += wb * vb.x;  accB.y += wb * vb.y;
        accB.z += wb * vb.z;  accB.w += wb * vb.w;
    }

    *reinterpret_cast<float4*>(&part[wid][4 * lane]) = accA;
    if (lane < 17)
        *reinterpret_cast<float4*>(&part[wid][128 + 4 * lane]) = accB;
    __syncthreads();

    if (tid < S) {
        float sum = 0.f;
#pragma unroll
        for (int w = 0; w < 8; w++) sum += part[w][tid];
        g_rai[blockIdx.x * 256 + tid] = sum;
    }
}

// ---------------------------------------------------------------------------
// Kernel B: softmax (redundant per CTA, deterministic) + weighted sum.
// Grid 1024 = (b, quarter), b descending so the kb re-read chases kernel A's
// L2 residue from the hot end.
// ---------------------------------------------------------------------------
__global__ __launch_bounds__(256) void readout_kernel(
    const float* __restrict__ kb,      // [B, D, S]
    float* __restrict__ out)           // [B, D]
{
    const int q    = blockIdx.x & 3;
    const int b    = (BATCH - 1) - (blockIdx.x >> 2);
    const int tid  = threadIdx.x;
    const int wid  = tid >> 5;
    const int lane = tid & 31;
    const int l2   = lane < 17 ? lane : 16;
    const float mB = lane < 17 ? 1.f : 0.f;

    __shared__ __align__(16) float rvi_s[208];
    __shared__ float red[8];

    // full rai = sum of 4 quarter-partials (fixed order -> deterministic)
    float rai = -INFINITY;
    if (tid < S) {
        float sum = 0.f;
#pragma unroll
        for (int k = 0; k < 4; k++) sum += g_rai[(b * 4 + k) * 256 + tid];
        rai = sum;
    }

    // ---- softmax over s ----
    float m = rai;
#pragma unroll
    for (int off = 16; off > 0; off >>= 1)
        m = fmaxf(m, __shfl_xor_sync(0xffffffff, m, off));
    if (lane == 0) red[wid] = m;
    __syncthreads();
    if (wid == 0) {
        float v = (lane < 8) ? red[lane] : -INFINITY;
#pragma unroll
        for (int off = 4; off > 0; off >>= 1)
            v = fmaxf(v, __shfl_xor_sync(0xffffffff, v, off));
        if (lane == 0) red[0] = v;
    }
    __syncthreads();
    const float gmax = red[0];
    __syncthreads();

    float p = (tid < S) ? expf(rai - gmax) : 0.f;
    float sacc = p;
#pragma unroll
    for (int off = 16; off > 0; off >>= 1)
        sacc += __shfl_xor_sync(0xffffffff, sacc, off);
    if (lane == 0) red[wid] = sacc;
    __syncthreads();
    if (wid == 0) {
        float v = (lane < 8) ? red[lane] : 0.f;
#pragma unroll
        for (int off = 4; off > 0; off >>= 1)
            v += __shfl_xor_sync(0xffffffff, v, off);
        if (lane == 0) red[0] = v;
    }
    __syncthreads();
    const float inv_sum = 1.f / red[0];
    if (tid < S) rvi_s[tid] = p * inv_sum;
    if (tid >= S && tid < 208) rvi_s[tid] = 0.f;
    __syncthreads();

    const float4 rA = *reinterpret_cast<const float4*>(&rvi_s[4 * lane]);
    const float4 rB = *reinterpret_cast<const float4*>(&rvi_s[128 + 4 * l2]);

    const float* __restrict__ base = kb + (size_t)b * (D * S);

    // out[e] = sum_s rvi[s] * kb[e][s]; 16 rows per warp
#pragma unroll 4
    for (int r = wid; r < 128; r += 8) {
        const int e = q * 128 + r;
        const float4* __restrict__ row = reinterpret_cast<const float4*>(base + e * S);
        float4 va = row[lane];
        float4 vb = row[32 + l2];
        float sum = va.x * rA.x + va.y * rA.y + va.z * rA.z + va.w * rA.w
                  + mB * (vb.x * rB.x + vb.y * rB.y + vb.z * rB.z + vb.w * rB.w);
#pragma unroll
        for (int off = 16; off > 0; off >>= 1)
            sum += __shfl_xor_sync(0xffffffff, sum, off);
        if (lane == 0) out[b * D + e] = sum;
    }
}

extern "C" void kernel_launch(void* const* d_in, const int* in_sizes, int n_in,
                              void* d_out, int out_size)
{
    const float* memory = (const float*)d_in[0];  // [B, D]
    const float* ctrl   = (const float*)d_in[1];  // [B, D]
    const float* kb     = (const float*)d_in[2];  // [B, D, S]
    const float* W      = (const float*)d_in[3];  // [D, D]
    // d_in[4] = b_concat: s-independent shift inside softmax -> drops out
    const float* w_attn = (const float*)d_in[5];  // [D]
    float* out = (float*)d_out;                   // [B, D]

    gemm_kernel<<<dim3(4, 16, 4), 256>>>(ctrl, W, w_attn);
    logits_kernel<<<4 * BATCH, 256>>>(kb, memory, ctrl, w_attn);
    readout_kernel<<<4 * BATCH, 256>>>(kb, out);
}

// round 6
// speedup vs baseline: 1.0516x; 1.0516x over previous
#include <cuda_runtime.h>
#include <math.h>
#include <stdint.h>

#define BATCH  256
#define D      512
#define S      196
#define NKQ    8            // k-slices in gemm

// device scratch (no allocs allowed)
__device__ float g_vp[NKQ][BATCH][D];     // k-slice partials of v = u @ W   (4 MB)
__device__ float g_rai[4 * BATCH * 256];  // per-quarter partial logits, stride 256

// ---------------------------------------------------------------------------
// GEMM partials: g_vp[kq][b][d] = sum_{e in 64-slice} u[b,e] * W[e,d],
//   u[b,e] = ctrl[b,e] * w_attn[e].
// Grid (4 d-tiles, 16 b-tiles, 8 k-slices) = 512 CTAs, 256 threads.
// Thread: dl = tid&127 (one d col), eh = tid>>7 (2-way split of 64-e slice).
// Inner iter: 1 LDG.32 + 4 broadcast LDS.128 + 16 FFMA  (16 MAC).
// ---------------------------------------------------------------------------
__global__ __launch_bounds__(256) void gemm_kernel(
    const float* __restrict__ ctrl,
    const float* __restrict__ W,       // [e, d] row-major
    const float* __restrict__ w_attn)
{
    __shared__ __align__(16) float u_s[64 * 16];     // [el][j]  4 KB
    __shared__ float part[2][16][128];               // 16 KB

    const int tid = threadIdx.x;
    const int dl  = tid & 127;
    const int eh  = tid >> 7;          // 0/1
    const int dq  = blockIdx.x;        // 0..3
    const int b0  = blockIdx.y * 16;
    const int kq  = blockIdx.z;        // 0..7
    const int d   = dq * 128 + dl;
    const int e0  = kq * 64;

    // u_s[el*16 + j] = ctrl[b0+j, e0+el] * w_attn[e0+el]   (coalesced reads)
    for (int idx = tid; idx < 1024; idx += 256) {
        int el = idx & 63, j = idx >> 6;
        u_s[el * 16 + j] = ctrl[(b0 + j) * D + e0 + el] * w_attn[e0 + el];
    }
    __syncthreads();

    float acc[16];
#pragma unroll
    for (int j = 0; j < 16; j++) acc[j] = 0.f;

    const int eb = eh * 32;
#pragma unroll 8
    for (int i = 0; i < 32; i++) {
        const int el = eb + i;
        const float wv = W[(e0 + el) * D + d];       // coalesced 128B/warp
        const float4 u0 = *reinterpret_cast<const float4*>(&u_s[el * 16 + 0]);
        const float4 u1 = *reinterpret_cast<const float4*>(&u_s[el * 16 + 4]);
        const float4 u2 = *reinterpret_cast<const float4*>(&u_s[el * 16 + 8]);
        const float4 u3 = *reinterpret_cast<const float4*>(&u_s[el * 16 + 12]);
        acc[0]  += wv * u0.x;  acc[1]  += wv * u0.y;
        acc[2]  += wv * u0.z;  acc[3]  += wv * u0.w;
        acc[4]  += wv * u1.x;  acc[5]  += wv * u1.y;
        acc[6]  += wv * u1.z;  acc[7]  += wv * u1.w;
        acc[8]  += wv * u2.x;  acc[9]  += wv * u2.y;
        acc[10] += wv * u2.z;  acc[11] += wv * u2.w;
        acc[12] += wv * u3.x;  acc[13] += wv * u3.y;
        acc[14] += wv * u3.z;  acc[15] += wv * u3.w;
    }

#pragma unroll
    for (int j = 0; j < 16; j++)
        part[eh][j][dl] = acc[j];
    __syncthreads();

    for (int o = tid; o < 2048; o += 256) {
        int j = o >> 7, dd = o & 127;
        g_vp[kq][b0 + j][dq * 128 + dd] = part[0][j][dd] + part[1][j][dd];
    }
}

// ---------------------------------------------------------------------------
// Kernel A: partial logits (finalize of w fused into the w_s load).
// Grid 1024 = (b, quarter): each CTA owns 128 d-rows, 8 warps, warp-per-row
// float4 loads. Streams kb from DRAM exactly once.
// ---------------------------------------------------------------------------
__global__ __launch_bounds__(256) void logits_kernel(
    const float* __restrict__ kb,      // [B, D, S]
    const float* __restrict__ memory,
    const float* __restrict__ ctrl,
    const float* __restrict__ w_attn)
{
    const int q    = blockIdx.x & 3;
    const int b    = blockIdx.x >> 2;
    const int tid  = threadIdx.x;
    const int wid  = tid >> 5;
    const int lane = tid & 31;
    const int l2   = lane < 17 ? lane : 16;     // clamp second segment
    const float mB = lane < 17 ? 1.f : 0.f;

    __shared__ float w_s[128];
    __shared__ __align__(16) float part[8][200];

    const float* __restrict__ base = kb + (size_t)b * (D * S) + (size_t)q * (128 * S);

    // fused finalize: w = memory * (sum of 8 k-slice partials) + ctrl * w_attn
    if (tid < 128) {
        const int dg = q * 128 + tid;
        float v = 0.f;
#pragma unroll
        for (int k = 0; k < NKQ; k++) v += g_vp[k][b][dg];
        w_s[tid] = memory[b * D + dg] * v + ctrl[b * D + dg] * w_attn[dg];
    }
    __syncthreads();

    float4 accA = make_float4(0.f, 0.f, 0.f, 0.f);
    float4 accB = make_float4(0.f, 0.f, 0.f, 0.f);

#pragma unroll 8
    for (int r = wid; r < 128; r += 8) {
        const float wv = w_s[r];
        const float4* __restrict__ row = reinterpret_cast<const float4*>(base + r * S);
        float4 va = row[lane];          // s = 4*lane..+3       (s < 128)
        float4 vb = row[32 + l2];       // s = 128+4*l2..+3     (s < 196)
        accA.x += wv * va.x;  accA.y += wv * va.y;
        accA.z += wv * va.z;  accA.w += wv * va.w;
        float wb = wv * mB;
        accB.x += wb * vb.x;  accB.y += wb * vb.y;
        accB.z += wb * vb.z;  accB.w += wb * vb.w;
    }

    *reinterpret_cast<float4*>(&part[wid][4 * lane]) = accA;
    if (lane < 17)
        *reinterpret_cast<float4*>(&part[wid][128 + 4 * lane]) = accB;
    __syncthreads();

    if (tid < S) {
        float sum = 0.f;
#pragma unroll
        for (int w = 0; w < 8; w++) sum += part[w][tid];
        g_rai[blockIdx.x * 256 + tid] = sum;
    }
}

// ---------------------------------------------------------------------------
// Kernel B: softmax (redundant per CTA, deterministic) + weighted sum.
// Grid 1024 = (b, quarter), b descending so the kb re-read chases kernel A's
// L2 residue from the hot end.
// ---------------------------------------------------------------------------
__global__ __launch_bounds__(256) void readout_kernel(
    const float* __restrict__ kb,      // [B, D, S]
    float* __restrict__ out)           // [B, D]
{
    const int q    = blockIdx.x & 3;
    const int b    = (BATCH - 1) - (blockIdx.x >> 2);
    const int tid  = threadIdx.x;
    const int wid  = tid >> 5;
    const int lane = tid & 31;
    const int l2   = lane < 17 ? lane : 16;
    const float mB = lane < 17 ? 1.f : 0.f;

    __shared__ __align__(16) float rvi_s[208];
    __shared__ float red[8];

    // full rai = sum of 4 quarter-partials (fixed order -> deterministic)
    float rai = -INFINITY;
    if (tid < S) {
        float sum = 0.f;
#pragma unroll
        for (int k = 0; k < 4; k++) sum += g_rai[(b * 4 + k) * 256 + tid];
        rai = sum;
    }

    // ---- softmax over s ----
    float m = rai;
#pragma unroll
    for (int off = 16; off > 0; off >>= 1)
        m = fmaxf(m, __shfl_xor_sync(0xffffffff, m, off));
    if (lane == 0) red[wid] = m;
    __syncthreads();
    if (wid == 0) {
        float v = (lane < 8) ? red[lane] : -INFINITY;
#pragma unroll
        for (int off = 4; off > 0; off >>= 1)
            v = fmaxf(v, __shfl_xor_sync(0xffffffff, v, off));
        if (lane == 0) red[0] = v;
    }
    __syncthreads();
    const float gmax = red[0];
    __syncthreads();

    float p = (tid < S) ? expf(rai - gmax) : 0.f;
    float sacc = p;
#pragma unroll
    for (int off = 16; off > 0; off >>= 1)
        sacc += __shfl_xor_sync(0xffffffff, sacc, off);
    if (lane == 0) red[wid] = sacc;
    __syncthreads();
    if (wid == 0) {
        float v = (lane < 8) ? red[lane] : 0.f;
#pragma unroll
        for (int off = 4; off > 0; off >>= 1)
            v += __shfl_xor_sync(0xffffffff, v, off);
        if (lane == 0) red[0] = v;
    }
    __syncthreads();
    const float inv_sum = 1.f / red[0];
    if (tid < S) rvi_s[tid] = p * inv_sum;
    if (tid >= S && tid < 208) rvi_s[tid] = 0.f;
    __syncthreads();

    const float4 rA = *reinterpret_cast<const float4*>(&rvi_s[4 * lane]);
    const float4 rB = *reinterpret_cast<const float4*>(&rvi_s[128 + 4 * l2]);

    const float* __restrict__ base = kb + (size_t)b * (D * S);

    // out[e] = sum_s rvi[s] * kb[e][s]; 16 rows per warp
#pragma unroll 8
    for (int r = wid; r < 128; r += 8) {
        const int e = q * 128 + r;
        const float4* __restrict__ row = reinterpret_cast<const float4*>(base + e * S);
        float4 va = row[lane];
        float4 vb = row[32 + l2];
        float sum = va.x * rA.x + va.y * rA.y + va.z * rA.z + va.w * rA.w
                  + mB * (vb.x * rB.x + vb.y * rB.y + vb.z * rB.z + vb.w * rB.w);
#pragma unroll
        for (int off = 16; off > 0; off >>= 1)
            sum += __shfl_xor_sync(0xffffffff, sum, off);
        if (lane == 0) out[b * D + e] = sum;
    }
}

extern "C" void kernel_launch(void* const* d_in, const int* in_sizes, int n_in,
                              void* d_out, int out_size)
{
    const float* memory = (const float*)d_in[0];  // [B, D]
    const float* ctrl   = (const float*)d_in[1];  // [B, D]
    const float* kb     = (const float*)d_in[2];  // [B, D, S]
    const float* W      = (const float*)d_in[3];  // [D, D]
    // d_in[4] = b_concat: s-independent shift inside softmax -> drops out
    const float* w_attn = (const float*)d_in[5];  // [D]
    float* out = (float*)d_out;                   // [B, D]

    gemm_kernel<<<dim3(4, 16, NKQ), 256>>>(ctrl, W, w_attn);
    logits_kernel<<<4 * BATCH, 256>>>(kb, memory, ctrl, w_attn);
    readout_kernel<<<4 * BATCH, 256>>>(kb, out);
}

// round 7
// speedup vs baseline: 1.3519x; 1.2855x over previous
#include <cuda_runtime.h>
#include <math.h>
#include <stdint.h>

#define BATCH  256
#define D      512
#define S      196
#define NKQ    16           // k-slices (32 e each)

// device scratch (no allocs allowed)
__device__ float g_vp[NKQ][BATCH][D];     // k-slice partials of v = u @ W   (8 MB)
__device__ float g_rai[4 * BATCH * 256];  // per-quarter partial logits, stride 256
__device__ unsigned int g_cnt[BATCH];     // per-batch completion counters

// ---------------------------------------------------------------------------
// GEMM partials: g_vp[kq][b][d] = sum_{e in 32-slice} u[b,e] * W[e,d],
//   u[b,e] = ctrl[b,e] * w_attn[e].
// Grid (32 b-tiles, 16 k-slices) = 512 CTAs, 256 threads.
// Thread = 8 batches x 4 d-cols (register tile, 32 acc); dl=tid&127 covers
// full D, eh=tid>>7 splits the 32-e slice in two (smem-reduced at the end).
// Inner iter: 1 LDG.128 (W) + 2 broadcast LDS.128 (u) + 32 FFMA.
// Also zeroes g_cnt for the fused kernel (stream-ordered).
// ---------------------------------------------------------------------------
__global__ __launch_bounds__(256) void gemm_kernel(
    const float* __restrict__ ctrl,
    const float* __restrict__ W,       // [e, d] row-major
    const float* __restrict__ w_attn)
{
    __shared__ __align__(16) float u_s[32 * 8];      // [el][j]   1 KB
    __shared__ __align__(16) float part[8 * 512];    // [j][d]   16 KB

    const int tid = threadIdx.x;
    const int dl  = tid & 127;
    const int eh  = tid >> 7;          // 0/1
    const int b0  = blockIdx.x * 8;
    const int kq  = blockIdx.y;
    const int e0  = kq * 32;
    const int d0  = dl * 4;

    if (blockIdx.x == 0 && blockIdx.y == 0 && tid < BATCH)
        g_cnt[tid] = 0;

    // u_s[el*8 + j] = ctrl[b0+j, e0+el] * w_attn[e0+el]
    {
        int el = tid & 31, j = tid >> 5;
        u_s[el * 8 + j] = ctrl[(b0 + j) * D + e0 + el] * w_attn[e0 + el];
    }
    __syncthreads();

    float acc[8][4];
#pragma unroll
    for (int j = 0; j < 8; j++)
#pragma unroll
        for (int i = 0; i < 4; i++) acc[j][i] = 0.f;

#pragma unroll 4
    for (int i = 0; i < 16; i++) {
        const int el = eh * 16 + i;
        const float4 w4 = *reinterpret_cast<const float4*>(W + (size_t)(e0 + el) * D + d0);
        const float4 ua = *reinterpret_cast<const float4*>(&u_s[el * 8]);
        const float4 ub = *reinterpret_cast<const float4*>(&u_s[el * 8 + 4]);
        acc[0][0] += ua.x * w4.x; acc[0][1] += ua.x * w4.y; acc[0][2] += ua.x * w4.z; acc[0][3] += ua.x * w4.w;
        acc[1][0] += ua.y * w4.x; acc[1][1] += ua.y * w4.y; acc[1][2] += ua.y * w4.z; acc[1][3] += ua.y * w4.w;
        acc[2][0] += ua.z * w4.x; acc[2][1] += ua.z * w4.y; acc[2][2] += ua.z * w4.z; acc[2][3] += ua.z * w4.w;
        acc[3][0] += ua.w * w4.x; acc[3][1] += ua.w * w4.y; acc[3][2] += ua.w * w4.z; acc[3][3] += ua.w * w4.w;
        acc[4][0] += ub.x * w4.x; acc[4][1] += ub.x * w4.y; acc[4][2] += ub.x * w4.z; acc[4][3] += ub.x * w4.w;
        acc[5][0] += ub.y * w4.x; acc[5][1] += ub.y * w4.y; acc[5][2] += ub.y * w4.z; acc[5][3] += ub.y * w4.w;
        acc[6][0] += ub.z * w4.x; acc[6][1] += ub.z * w4.y; acc[6][2] += ub.z * w4.z; acc[6][3] += ub.z * w4.w;
        acc[7][0] += ub.w * w4.x; acc[7][1] += ub.w * w4.y; acc[7][2] += ub.w * w4.z; acc[7][3] += ub.w * w4.w;
    }

    // eh=1 spills to smem; eh=0 adds and writes g_vp
    if (eh == 1) {
#pragma unroll
        for (int j = 0; j < 8; j++)
            *reinterpret_cast<float4*>(&part[j * 512 + d0]) =
                make_float4(acc[j][0], acc[j][1], acc[j][2], acc[j][3]);
    }
    __syncthreads();
    if (eh == 0) {
#pragma unroll
        for (int j = 0; j < 8; j++) {
            float4 p = *reinterpret_cast<const float4*>(&part[j * 512 + d0]);
            *reinterpret_cast<float4*>(&g_vp[kq][b0 + j][d0]) =
                make_float4(acc[j][0] + p.x, acc[j][1] + p.y,
                            acc[j][2] + p.z, acc[j][3] + p.w);
        }
    }
}

// ---------------------------------------------------------------------------
// Fused kernel: per-(b,quarter) CTA computes partial logits (streaming its kb
// tile from DRAM), signals via per-batch counter, acquire-spins for the other
// 3 quarters, softmaxes (redundant, deterministic), then does the weighted
// sum re-reading its own kb tile — guaranteed L2-hot. Overlaps DRAM pass of
// late batches with L2 pass of early batches.
// ---------------------------------------------------------------------------
__global__ __launch_bounds__(256) void fused_kernel(
    const float* __restrict__ kb,      // [B, D, S]
    const float* __restrict__ memory,
    const float* __restrict__ ctrl,
    const float* __restrict__ w_attn,
    float* __restrict__ out)           // [B, D]
{
    const int q    = blockIdx.x & 3;
    const int b    = blockIdx.x >> 2;
    const int tid  = threadIdx.x;
    const int wid  = tid >> 5;
    const int lane = tid & 31;
    const int l2   = lane < 17 ? lane : 16;     // clamp second segment
    const float mB = lane < 17 ? 1.f : 0.f;

    __shared__ float w_s[128];
    __shared__ __align__(16) float part[8][200];
    __shared__ __align__(16) float rvi_s[208];
    __shared__ float red[8];

    const float* __restrict__ base = kb + (size_t)b * (D * S) + (size_t)q * (128 * S);

    // finalize: w = memory * (sum of k-slice partials) + ctrl * w_attn
    if (tid < 128) {
        const int dg = q * 128 + tid;
        float v = 0.f;
#pragma unroll
        for (int k = 0; k < NKQ; k++) v += g_vp[k][b][dg];
        w_s[tid] = memory[b * D + dg] * v + ctrl[b * D + dg] * w_attn[dg];
    }
    __syncthreads();

    // ---- Pass 1: partial logits over my 128 d-rows ----
    float4 accA = make_float4(0.f, 0.f, 0.f, 0.f);
    float4 accB = make_float4(0.f, 0.f, 0.f, 0.f);

#pragma unroll 4
    for (int r = wid; r < 128; r += 8) {
        const float wv = w_s[r];
        const float4* __restrict__ row = reinterpret_cast<const float4*>(base + r * S);
        float4 va = row[lane];          // s = 4*lane..+3       (s < 128)
        float4 vb = row[32 + l2];       // s = 128+4*l2..+3     (s < 196)
        accA.x += wv * va.x;  accA.y += wv * va.y;
        accA.z += wv * va.z;  accA.w += wv * va.w;
        float wb = wv * mB;
        accB.x += wb * vb.x;  accB.y += wb * vb.y;
        accB.z += wb * vb.z;  accB.w += wb * vb.w;
    }

    *reinterpret_cast<float4*>(&part[wid][4 * lane]) = accA;
    if (lane < 17)
        *reinterpret_cast<float4*>(&part[wid][128 + 4 * lane]) = accB;
    __syncthreads();

    if (tid < S) {
        float sum = 0.f;
#pragma unroll
        for (int w = 0; w < 8; w++) sum += part[w][tid];
        g_rai[blockIdx.x * 256 + tid] = sum;
    }
    __syncthreads();

    // ---- signal + spin: all 4 quarters of batch b done? ----
    if (tid == 0) {
        __threadfence();                               // release g_rai
        atomicAdd(&g_cnt[b], 1u);
    }
    {
        unsigned v;
        do {
            asm volatile("ld.acquire.gpu.global.u32 %0, [%1];"
                         : "=r"(v) : "l"(&g_cnt[b]) : "memory");
            if (v < 4u) __nanosleep(64);
        } while (v < 4u);
    }

    // full rai = sum of 4 quarter-partials (fixed order -> deterministic)
    float rai = -INFINITY;
    if (tid < S) {
        float sum = 0.f;
#pragma unroll
        for (int k = 0; k < 4; k++) sum += g_rai[(b * 4 + k) * 256 + tid];
        rai = sum;
    }

    // ---- softmax over s ----
    float m = rai;
#pragma unroll
    for (int off = 16; off > 0; off >>= 1)
        m = fmaxf(m, __shfl_xor_sync(0xffffffff, m, off));
    if (lane == 0) red[wid] = m;
    __syncthreads();
    if (wid == 0) {
        float v = (lane < 8) ? red[lane] : -INFINITY;
#pragma unroll
        for (int off = 4; off > 0; off >>= 1)
            v = fmaxf(v, __shfl_xor_sync(0xffffffff, v, off));
        if (lane == 0) red[0] = v;
    }
    __syncthreads();
    const float gmax = red[0];
    __syncthreads();

    float p = (tid < S) ? expf(rai - gmax) : 0.f;
    float sacc = p;
#pragma unroll
    for (int off = 16; off > 0; off >>= 1)
        sacc += __shfl_xor_sync(0xffffffff, sacc, off);
    if (lane == 0) red[wid] = sacc;
    __syncthreads();
    if (wid == 0) {
        float v = (lane < 8) ? red[lane] : 0.f;
#pragma unroll
        for (int off = 4; off > 0; off >>= 1)
            v += __shfl_xor_sync(0xffffffff, v, off);
        if (lane == 0) red[0] = v;
    }
    __syncthreads();
    const float inv_sum = 1.f / red[0];
    if (tid < S) rvi_s[tid] = p * inv_sum;
    if (tid >= S && tid < 208) rvi_s[tid] = 0.f;
    __syncthreads();

    const float4 rA = *reinterpret_cast<const float4*>(&rvi_s[4 * lane]);
    const float4 rB = *reinterpret_cast<const float4*>(&rvi_s[128 + 4 * l2]);

    // ---- Pass 2: weighted sum over my own (L2-hot) kb tile ----
#pragma unroll 4
    for (int r = wid; r < 128; r += 8) {
        const int e = q * 128 + r;
        const float4* __restrict__ row = reinterpret_cast<const float4*>(base + r * S);
        float4 va = row[lane];
        float4 vb = row[32 + l2];
        float sum = va.x * rA.x + va.y * rA.y + va.z * rA.z + va.w * rA.w
                  + mB * (vb.x * rB.x + vb.y * rB.y + vb.z * rB.z + vb.w * rB.w);
#pragma unroll
        for (int off = 16; off > 0; off >>= 1)
            sum += __shfl_xor_sync(0xffffffff, sum, off);
        if (lane == 0) out[b * D + e] = sum;
    }
}

extern "C" void kernel_launch(void* const* d_in, const int* in_sizes, int n_in,
                              void* d_out, int out_size)
{
    const float* memory = (const float*)d_in[0];  // [B, D]
    const float* ctrl   = (const float*)d_in[1];  // [B, D]
    const float* kb     = (const float*)d_in[2];  // [B, D, S]
    const float* W      = (const float*)d_in[3];  // [D, D]
    // d_in[4] = b_concat: s-independent shift inside softmax -> drops out
    const float* w_attn = (const float*)d_in[5];  // [D]
    float* out = (float*)d_out;                   // [B, D]

    gemm_kernel<<<dim3(32, NKQ), 256>>>(ctrl, W, w_attn);
    fused_kernel<<<4 * BATCH, 256>>>(kb, memory, ctrl, w_attn, out);
}